// round 4
// baseline (speedup 1.0000x reference)
#include <cuda_runtime.h>
#include <math.h>

#define NUM_L1 16
#define NUM_L2 8
#define IN_C   30             // 120 floats = 30 float4 chunks
#define OUT_C  51             // 204 floats = 51 float4 chunks
#define N_VD   120
#define N_TD   28
#define EPS_N  1e-6f
#define WPB    8              // warps per block

// output float offsets
#define O_VN   32
#define O_TN   48
#define O_VD   56
#define O_TD   176

__global__ __launch_bounds__(32 * WPB)
void invariant_extractor_kernel(const float4* __restrict__ h4,
                                float4* __restrict__ out4,
                                int n_atoms) {
    __shared__ float4 s_in4 [WPB][22];        // vec+tens region of input row (chunks 8..29)
    __shared__ float4 s_out4[WPB][OUT_C];     // chunks 8..50 used
    __shared__ float4 s_v   [WPB][NUM_L1];    // normalized vecs (padded float4)
    __shared__ float4 s_t   [WPB][NUM_L2][2]; // normalized tens (padded to 8 floats)

    const int w    = threadIdx.x >> 5;
    const int lane = threadIdx.x & 31;
    const int atom = blockIdx.x * WPB + w;
    if (atom >= n_atoms) return;

    // ---- coalesced vectorized load; scalars (chunks 0..7) stay in register ----
    const float4* row4 = h4 + (size_t)atom * IN_C;
    float4 v = make_float4(0.f, 0.f, 0.f, 0.f);
    if (lane < IN_C) {
        v = row4[lane];
        if (lane >= 8) s_in4[w][lane - 8] = v;
    }
    __syncwarp();

    float* si = (float*)s_in4[w];   // si[0] == input float 32 (vec region start)
    float* so = (float*)s_out4[w];

    // ---- norms; normalized components kept in registers + padded smem copy ----
    float ax = 0.f, ay = 0.f, az = 0.f, a3 = 0.f, a4 = 0.f;
    if (lane < NUM_L1) {
        float x = si[3 * lane], y = si[3 * lane + 1], z = si[3 * lane + 2];
        float nrm = fmaxf(sqrtf(x * x + y * y + z * z), EPS_N);
        so[O_VN + lane] = nrm;
        float inv = 1.0f / nrm;
        ax = x * inv; ay = y * inv; az = z * inv;
        s_v[w][lane] = make_float4(ax, ay, az, 0.f);
    } else if (lane < NUM_L1 + NUM_L2) {
        const int t = lane - NUM_L1;
        const float* b = si + 48 + 5 * t;
        float c0 = b[0], c1 = b[1], c2 = b[2], c3 = b[3], c4 = b[4];
        float nrm = fmaxf(sqrtf(c0*c0 + c1*c1 + c2*c2 + c3*c3 + c4*c4), EPS_N);
        so[O_TN + t] = nrm;
        float inv = 1.0f / nrm;
        ax = c0 * inv; ay = c1 * inv; az = c2 * inv; a3 = c3 * inv; a4 = c4 * inv;
        s_t[w][t][0] = make_float4(ax, ay, az, a3);
        ((float*)s_t[w][t])[4] = a4;
    }
    __syncwarp();

    // ---- pair dots: gram-row loops with uniform-address (broadcast) smem reads ----
    if (lane < NUM_L1) {
        const int i = lane;
        // p(i,j) = O_VD + i*15 - i(i-1)/2 + (j - i - 1)
        const int base = O_VD + i * 15 - (i * (i - 1)) / 2 - i - 1;
        #pragma unroll
        for (int j = 1; j < NUM_L1; j++) {
            if (i < j) {
                const float4 b = s_v[w][j];            // broadcast read
                float d = ax * b.x + ay * b.y + az * b.z;
                so[base + j] = fminf(fmaxf(d, -1.0f), 1.0f);
            }
        }
    } else if (lane < NUM_L1 + NUM_L2) {
        const int i = lane - NUM_L1;
        const int base = O_TD + i * 7 - (i * (i - 1)) / 2 - i - 1;
        #pragma unroll
        for (int j = 1; j < NUM_L2; j++) {
            if (i < j) {
                const float* bp = (const float*)s_t[w][j];  // broadcast read
                const float4 b0 = *(const float4*)bp;
                float d = ax * b0.x + ay * b0.y + az * b0.z + a3 * b0.w + a4 * bp[4];
                so[base + j] = fminf(fmaxf(d, -1.0f), 1.0f);
            }
        }
    }
    __syncwarp();

    // ---- coalesced store: scalars direct from register, rest from smem ----
    float4* orow = out4 + (size_t)atom * OUT_C;
    if (lane < 8) orow[lane] = v;                         // chunks 0..7
    orow[8 + lane] = s_out4[w][8 + lane];                 // chunks 8..39
    if (lane < OUT_C - 40) orow[40 + lane] = s_out4[w][40 + lane];  // chunks 40..50
}

extern "C" void kernel_launch(void* const* d_in, const int* in_sizes, int n_in,
                              void* d_out, int out_size) {
    const float4* h = (const float4*)d_in[0];
    float4* out = (float4*)d_out;
    const int n_atoms = in_sizes[0] / 120;

    const int threads = 32 * WPB;
    const int blocks = (n_atoms + WPB - 1) / WPB;
    invariant_extractor_kernel<<<blocks, threads>>>(h, out, n_atoms);
}

// round 5
// speedup vs baseline: 1.4395x; 1.4395x over previous
#include <cuda_runtime.h>
#include <math.h>

#define NUM_L1 16
#define NUM_L2 8
#define IN_C   30             // 120 floats = 30 float4 chunks
#define OUT_C  51             // 204 floats = 51 float4 chunks
#define N_VD   120
#define N_TD   28
#define EPS_N  1e-6f
#define WPB    8              // warps per block

// output float offsets
#define O_VN   32
#define O_TN   48
#define O_VD   56
#define O_TD   176

__global__ __launch_bounds__(32 * WPB)
void invariant_extractor_kernel(const float4* __restrict__ h4,
                                float4* __restrict__ out4,
                                int n_atoms) {
    __shared__ float4 s_in4 [WPB][22];        // vec+tens region of input row (chunks 8..29)
    __shared__ float4 s_out4[WPB][OUT_C];     // chunks 8..50 used
    __shared__ unsigned char s_vp[N_VD];      // (i<<4)|j
    __shared__ unsigned char s_tp[N_TD];      // (i<<3)|j

    const int tid  = threadIdx.x;
    const int w    = tid >> 5;
    const int lane = tid & 31;
    const int atom = blockIdx.x * WPB + w;
    const bool valid = (atom < n_atoms);

    // ---- coalesced vectorized load; scalars (chunks 0..7) stay in register ----
    float4 v = make_float4(0.f, 0.f, 0.f, 0.f);
    if (valid && lane < IN_C) {
        v = h4[(size_t)atom * IN_C + lane];
        if (lane >= 8) s_in4[w][lane - 8] = v;
    }

    // ---- build pair tables once per block (plain ALU + STS; off the const port) ----
    if (tid < N_VD + N_TD) {
        int p, n;
        if (tid < N_VD) { p = tid; n = NUM_L1; }
        else            { p = tid - N_VD; n = NUM_L2; }
        int i = 0, rem = p;
        while (rem >= n - 1 - i) { rem -= n - 1 - i; i++; }
        int j = i + 1 + rem;
        if (tid < N_VD) s_vp[tid]        = (unsigned char)((i << 4) | j);
        else            s_tp[tid - N_VD] = (unsigned char)((i << 3) | j);
    }
    __syncthreads();
    if (!valid) return;

    const float* si = (const float*)s_in4[w];   // si[0] == input float 32
    float*       so = (float*)s_out4[w];

    // ---- norms: unified single path, lanes 0..23; normalized comps stay in regs ----
    float a0 = 0.f, a1 = 0.f, a2 = 0.f, a3 = 0.f, a4 = 0.f;
    if (lane < NUM_L1 + NUM_L2) {
        const bool isv = lane < NUM_L1;
        const int base = isv ? 3 * lane : 48 + 5 * (lane - NUM_L1);
        float c0 = si[base], c1 = si[base + 1], c2 = si[base + 2];
        float c3 = isv ? 0.f : si[base + 3];
        float c4 = isv ? 0.f : si[base + 4];
        float nrm = fmaxf(sqrtf(c0*c0 + c1*c1 + c2*c2 + c3*c3 + c4*c4), EPS_N);
        so[isv ? (O_VN + lane) : (O_TN + lane - NUM_L1)] = nrm;
        float inv = 1.0f / nrm;
        a0 = c0 * inv; a1 = c1 * inv; a2 = c2 * inv; a3 = c3 * inv; a4 = c4 * inv;
    }
    __syncwarp();

    // ---- vector pair dots: 4 per lane; operands via shfl.idx (no smem reads) ----
    #pragma unroll
    for (int u = 0; u < 4; u++) {
        const int p = lane + 32 * u;
        const bool act = (p < N_VD);
        const int ij = act ? s_vp[p] : 0;
        const int i = ij >> 4;
        const int j = ij & 15;
        float bx = __shfl_sync(0xffffffffu, a0, i);
        float by = __shfl_sync(0xffffffffu, a1, i);
        float bz = __shfl_sync(0xffffffffu, a2, i);
        float cx = __shfl_sync(0xffffffffu, a0, j);
        float cy = __shfl_sync(0xffffffffu, a1, j);
        float cz = __shfl_sync(0xffffffffu, a2, j);
        if (act) {
            float d = bx * cx + by * cy + bz * cz;
            so[O_VD + p] = fminf(fmaxf(d, -1.0f), 1.0f);
        }
    }

    // ---- tensor pair dots: lanes 0..27; operands via shfl.idx from lanes 16..23 ----
    {
        const bool act = (lane < N_TD);
        const int ij = act ? s_tp[lane] : 0;
        const int i = NUM_L1 + (ij >> 3);
        const int j = NUM_L1 + (ij & 7);
        float b0 = __shfl_sync(0xffffffffu, a0, i);
        float b1 = __shfl_sync(0xffffffffu, a1, i);
        float b2 = __shfl_sync(0xffffffffu, a2, i);
        float b3 = __shfl_sync(0xffffffffu, a3, i);
        float b4 = __shfl_sync(0xffffffffu, a4, i);
        float c0 = __shfl_sync(0xffffffffu, a0, j);
        float c1 = __shfl_sync(0xffffffffu, a1, j);
        float c2 = __shfl_sync(0xffffffffu, a2, j);
        float c3 = __shfl_sync(0xffffffffu, a3, j);
        float c4 = __shfl_sync(0xffffffffu, a4, j);
        if (act) {
            float d = b0*c0 + b1*c1 + b2*c2 + b3*c3 + b4*c4;
            so[O_TD + lane] = fminf(fmaxf(d, -1.0f), 1.0f);
        }
    }
    __syncwarp();

    // ---- coalesced store: scalars direct from register, rest from smem ----
    float4* orow = out4 + (size_t)atom * OUT_C;
    if (lane < 8) orow[lane] = v;                                    // chunks 0..7
    orow[8 + lane] = s_out4[w][8 + lane];                            // chunks 8..39
    if (lane < OUT_C - 40) orow[40 + lane] = s_out4[w][40 + lane];   // chunks 40..50
}

extern "C" void kernel_launch(void* const* d_in, const int* in_sizes, int n_in,
                              void* d_out, int out_size) {
    const float4* h = (const float4*)d_in[0];
    float4* out = (float4*)d_out;
    const int n_atoms = in_sizes[0] / 120;

    const int threads = 32 * WPB;
    const int blocks = (n_atoms + WPB - 1) / WPB;
    invariant_extractor_kernel<<<blocks, threads>>>(h, out, n_atoms);
}

// round 6
// speedup vs baseline: 1.4820x; 1.0295x over previous
#include <cuda_runtime.h>
#include <math.h>

#define NUM_L1 16
#define NUM_L2 8
#define IN_C   30             // 120 floats = 30 float4 chunks
#define OUT_C  51             // 204 floats
#define N_VD   120
#define N_TD   28
#define EPS_N  1e-6f
#define WPB    8

// output float offsets
#define O_VN   32             // norms (vec then tens, 24 floats, contiguous)
#define O_VD   56
#define O_TD   176

__global__ __launch_bounds__(32 * WPB)
void invariant_extractor_kernel(const float4* __restrict__ h4,
                                float* __restrict__ out,
                                int n_atoms) {
    __shared__ float4 s_in4[WPB][22];          // input chunks 8..29 (vec+tens region)
    __shared__ unsigned char s_vp[128];        // vec pair table, linear p -> (i<<4)|j
    __shared__ unsigned char s_tp[32];         // tens pair table, p -> (i<<3)|j

    const int tid  = threadIdx.x;
    const int w    = tid >> 5;
    const int lane = tid & 31;
    const int atom = blockIdx.x * WPB + w;
    const bool valid = (atom < n_atoms);

    // ---- coalesced vectorized load; scalar chunks 0..7 stay in register ----
    float4 v = make_float4(0.f, 0.f, 0.f, 0.f);
    if (valid && lane < IN_C) {
        v = h4[(size_t)atom * IN_C + lane];
        if (lane >= 8) s_in4[w][lane - 8] = v;
    }

    // ---- build pair tables once per block ----
    if (tid < N_VD + N_TD) {
        int p, n;
        if (tid < N_VD) { p = tid; n = NUM_L1; }
        else            { p = tid - N_VD; n = NUM_L2; }
        int i = 0, rem = p;
        while (rem >= n - 1 - i) { rem -= n - 1 - i; i++; }
        int j = i + 1 + rem;
        if (tid < N_VD) s_vp[tid]        = (unsigned char)((i << 4) | j);
        else            s_tp[tid - N_VD] = (unsigned char)((i << 3) | j);
    }
    __syncthreads();
    if (!valid) return;

    const float* si = (const float*)s_in4[w];   // si[0] == input float 32
    float* orow = out + (size_t)atom * 204;

    // ---- norms: lanes 0..23, components kept in registers ----
    float a0 = 0.f, a1 = 0.f, a2 = 0.f, a3 = 0.f, a4 = 0.f;
    if (lane < NUM_L1 + NUM_L2) {
        const bool isv = lane < NUM_L1;
        const int base = isv ? 3 * lane : 48 + 5 * (lane - NUM_L1);
        float c0 = si[base], c1 = si[base + 1], c2 = si[base + 2];
        float c3 = isv ? 0.f : si[base + 3];
        float c4 = isv ? 0.f : si[base + 4];
        float nrm = fmaxf(sqrtf(c0*c0 + c1*c1 + c2*c2 + c3*c3 + c4*c4), EPS_N);
        orow[O_VN + lane] = nrm;                       // out[32..55], coalesced
        float inv = 1.0f / nrm;
        a0 = c0 * inv; a1 = c1 * inv; a2 = c2 * inv; a3 = c3 * inv; a4 = c4 * inv;
    }
    __syncwarp();

    // ---- scalars: direct STG.128 from the load register ----
    if (lane < 8) ((float4*)orow)[lane] = v;           // out[0..31]

    // ---- vector pair dots: pairs p = 4*lane+u, one packed table word per lane ----
    {
        unsigned int w4 = (lane < 30) ? ((const unsigned int*)s_vp)[lane] : 0u;
        float4 res;
        float* r = (float*)&res;
        #pragma unroll
        for (int u = 0; u < 4; u++) {
            const int ij = (w4 >> (8 * u)) & 0xff;
            const int i = ij >> 4;
            const int j = ij & 15;
            float bx = __shfl_sync(0xffffffffu, a0, i);
            float by = __shfl_sync(0xffffffffu, a1, i);
            float bz = __shfl_sync(0xffffffffu, a2, i);
            float cx = __shfl_sync(0xffffffffu, a0, j);
            float cy = __shfl_sync(0xffffffffu, a1, j);
            float cz = __shfl_sync(0xffffffffu, a2, j);
            float d = bx * cx + by * cy + bz * cz;
            r[u] = fminf(fmaxf(d, -1.0f), 1.0f);
        }
        if (lane < 30)
            *(float4*)(orow + O_VD + 4 * lane) = res;  // out[56..175], one STG.128
    }

    // ---- tensor pair dots: p = lane (lanes 0..27), sources are lanes 16..23 ----
    {
        const bool act = (lane < N_TD);
        const int ij = act ? s_tp[lane] : 0;
        const int i = NUM_L1 + (ij >> 3);
        const int j = NUM_L1 + (ij & 7);
        float b0 = __shfl_sync(0xffffffffu, a0, i);
        float b1 = __shfl_sync(0xffffffffu, a1, i);
        float b2 = __shfl_sync(0xffffffffu, a2, i);
        float b3 = __shfl_sync(0xffffffffu, a3, i);
        float b4 = __shfl_sync(0xffffffffu, a4, i);
        float c0 = __shfl_sync(0xffffffffu, a0, j);
        float c1 = __shfl_sync(0xffffffffu, a1, j);
        float c2 = __shfl_sync(0xffffffffu, a2, j);
        float c3 = __shfl_sync(0xffffffffu, a3, j);
        float c4 = __shfl_sync(0xffffffffu, a4, j);
        if (act) {
            float d = b0*c0 + b1*c1 + b2*c2 + b3*c3 + b4*c4;
            orow[O_TD + lane] = fminf(fmaxf(d, -1.0f), 1.0f);  // out[176..203]
        }
    }
}

extern "C" void kernel_launch(void* const* d_in, const int* in_sizes, int n_in,
                              void* d_out, int out_size) {
    const float4* h = (const float4*)d_in[0];
    float* out = (float*)d_out;
    const int n_atoms = in_sizes[0] / 120;

    const int threads = 32 * WPB;
    const int blocks = (n_atoms + WPB - 1) / WPB;
    invariant_extractor_kernel<<<blocks, threads>>>(h, out, n_atoms);
}